// round 1
// baseline (speedup 1.0000x reference)
#include <cuda_runtime.h>
#include <cuda_bf16.h>
#include <cstdint>

// Problem constants (GB300 MolDis)
#define NMAX 1048576   // nodes
#define EMAX 4194304   // edges
#define DD   32        // feature dim
#define RR   4         // relations

// Scratch: __device__ globals (no allocation allowed in kernel_launch)
__device__ float g_agg[(size_t)NMAX * RR * DD];  // 512 MB: per-(dst,rel) aggregated h[src]
__device__ float g_h1[(size_t)NMAX * DD];        // 128 MB
__device__ float g_h2[(size_t)NMAX * DD];        // 128 MB

// ---------------------------------------------------------------------------
// Edge kernel: agg[dst][etype][:] += h[src][:]
// 8 threads per edge, each handles 4 floats via 128-bit vector reduction.
// ---------------------------------------------------------------------------
__global__ void edge_kernel(const float* __restrict__ h,
                            const int* __restrict__ src,
                            const int* __restrict__ dst,
                            const int* __restrict__ et,
                            int E)
{
    int t = blockIdx.x * blockDim.x + threadIdx.x;
    int e = t >> 3;
    if (e >= E) return;
    int q = t & 7;

    int s = __ldg(src + e);
    int d = __ldg(dst + e);
    int r = __ldg(et + e);

    float4 v = __ldg(reinterpret_cast<const float4*>(h) + (size_t)s * 8 + q);
    float* p = g_agg + (((size_t)d * RR + r) * DD) + q * 4;
    asm volatile("red.global.add.v4.f32 [%0], {%1, %2, %3, %4};"
                 :: "l"(p), "f"(v.x), "f"(v.y), "f"(v.z), "f"(v.w)
                 : "memory");
}

// ---------------------------------------------------------------------------
// Combine kernel: hout[n][o] = relu( sum_{r,i} agg[n][r][i]*W[r][i][o]
//                                    + sum_i hin[n][i]*Wl[i][o] + bias[o] )
// Warp per node; lane = output column o. W column [160] kept in registers.
// Inputs broadcast across the warp with shuffles; 4 accumulators for ILP.
// ---------------------------------------------------------------------------
#define DOT32(val, base)                                                          \
    _Pragma("unroll")                                                             \
    for (int i = 0; i < 32; i += 4) {                                             \
        acc0 = fmaf(__shfl_sync(0xffffffffu, (val), i + 0), w[(base) + i + 0], acc0); \
        acc1 = fmaf(__shfl_sync(0xffffffffu, (val), i + 1), w[(base) + i + 1], acc1); \
        acc2 = fmaf(__shfl_sync(0xffffffffu, (val), i + 2), w[(base) + i + 2], acc2); \
        acc3 = fmaf(__shfl_sync(0xffffffffu, (val), i + 3), w[(base) + i + 3], acc3); \
    }

__global__ void __launch_bounds__(256, 1)
combine_kernel(const float* __restrict__ hin,
               float* __restrict__ hout,
               const float* __restrict__ W,     // [R, D, D] = [4,32,32]
               const float* __restrict__ Wl,    // [D, D]
               const float* __restrict__ bias,  // [D]
               int N)
{
    const int lane   = threadIdx.x & 31;
    const int warpId = (blockIdx.x * blockDim.x + threadIdx.x) >> 5;
    const int nWarps = (gridDim.x * blockDim.x) >> 5;

    // Load this lane's weight column into registers (constant indices after unroll)
    float w[160];
#pragma unroll
    for (int k = 0; k < 128; k++) w[k] = __ldg(W + k * 32 + lane);   // W[r][i][lane], k=r*32+i
#pragma unroll
    for (int i = 0; i < 32; i++) w[128 + i] = __ldg(Wl + i * 32 + lane);
    const float b = __ldg(bias + lane);

    for (int n = warpId; n < N; n += nWarps) {
        const float* aggn = g_agg + (size_t)n * (RR * DD);
        float a0 = aggn[lane];
        float a1 = aggn[32 + lane];
        float a2 = aggn[64 + lane];
        float a3 = aggn[96 + lane];
        float x  = hin[(size_t)n * DD + lane];

        float acc0 = b, acc1 = 0.0f, acc2 = 0.0f, acc3 = 0.0f;
        DOT32(a0, 0)
        DOT32(a1, 32)
        DOT32(a2, 64)
        DOT32(a3, 96)
        DOT32(x, 128)

        float acc = (acc0 + acc1) + (acc2 + acc3);
        hout[(size_t)n * DD + lane] = fmaxf(acc, 0.0f);
    }
}

// ---------------------------------------------------------------------------
// Mean kernel: out[m][o] = mean_{a<32} h[(m*32+a)][o]
// ---------------------------------------------------------------------------
__global__ void mean_kernel(const float* __restrict__ h,
                            float* __restrict__ out,
                            int M)
{
    int lane = threadIdx.x & 31;
    int m = (blockIdx.x * blockDim.x + threadIdx.x) >> 5;
    if (m >= M) return;
    float s = 0.0f;
#pragma unroll
    for (int a = 0; a < 32; a++)
        s += h[((size_t)m * 32 + a) * DD + lane];
    out[(size_t)m * DD + lane] = s * (1.0f / 32.0f);
}

// ---------------------------------------------------------------------------
extern "C" void kernel_launch(void* const* d_in, const int* in_sizes, int n_in,
                              void* d_out, int out_size)
{
    const float* x    = (const float*)d_in[0];
    const float* W    = (const float*)d_in[1];
    const float* Wl   = (const float*)d_in[2];
    const float* bias = (const float*)d_in[3];
    const int*   src  = (const int*)d_in[4];
    const int*   dst  = (const int*)d_in[5];
    const int*   et   = (const int*)d_in[6];
    float* out = (float*)d_out;

    const int N = in_sizes[0] / DD;
    const int E = in_sizes[4];
    const int M = out_size / DD;   // number of molecules

    void *aggPtr = nullptr, *h1Ptr = nullptr, *h2Ptr = nullptr;
    cudaGetSymbolAddress(&aggPtr, g_agg);
    cudaGetSymbolAddress(&h1Ptr, g_h1);
    cudaGetSymbolAddress(&h2Ptr, g_h2);
    float* h1 = (float*)h1Ptr;
    float* h2 = (float*)h2Ptr;

    const size_t aggBytes = (size_t)N * RR * DD * sizeof(float);
    const int edgeBlocks = (E * 8 + 255) / 256;
    const int combBlocks = 2048;
    const int meanBlocks = (M * 32 + 255) / 256;

    // ---- Layer 1 ----
    cudaMemsetAsync(aggPtr, 0, aggBytes, 0);
    edge_kernel<<<edgeBlocks, 256>>>(x, src, dst, et, E);
    combine_kernel<<<combBlocks, 256>>>(x, h1, W, Wl, bias, N);

    // ---- Layer 2 ----
    cudaMemsetAsync(aggPtr, 0, aggBytes, 0);
    edge_kernel<<<edgeBlocks, 256>>>(h1, src, dst, et, E);
    combine_kernel<<<combBlocks, 256>>>(h1, h2, W, Wl, bias, N);

    // ---- Per-molecule mean ----
    mean_kernel<<<meanBlocks, 256>>>(h2, out, M);
}

// round 2
// speedup vs baseline: 1.4325x; 1.4325x over previous
#include <cuda_runtime.h>
#include <cuda_bf16.h>
#include <cstdint>

#define NMAX 1048576
#define EMAX 4194304
#define DD   32
#define RR   4

// Scratch (__device__ globals; no allocation allowed in kernel_launch)
__device__ float g_hw[(size_t)NMAX * RR * DD];   // 512 MB: per-node per-relation projections
__device__ float g_aggA[(size_t)NMAX * DD];      // 128 MB: layer-1 pre-activation
__device__ float g_aggB[(size_t)NMAX * DD];      // 128 MB: layer-2 pre-activation

// ---- f32x2 packed helpers (64-bit carriers) --------------------------------
#define FMA2(d, a, b, c) asm("fma.rn.f32x2 %0, %1, %2, %3;" : "=l"(d) : "l"(a), "l"(b), "l"(c))
#define ADD2(d, a, b)    asm("add.rn.f32x2 %0, %1, %2;"     : "=l"(d) : "l"(a), "l"(b))
#define PACK2(d, lo, hi) asm("mov.b64 %0, {%1, %2};"        : "=l"(d) : "f"(lo), "f"(hi))
#define UNPACK2(lo, hi, s) asm("mov.b64 {%0, %1}, %2;"      : "=f"(lo), "=f"(hi) : "l"(s))

// ---------------------------------------------------------------------------
// proj kernel: for each node n,
//   hw[n][r][o]  = sum_k h[n][k] * W[r][k][o]        (r < 4)
//   agg[n][o]    = sum_k h[n][k] * Wl[k][o] + bias[o]   (self-loop init)
// Warp per node; lane = output column o. K=32 broadcasts via shuffle,
// relation pairs (0,1) and (2,3) computed with packed f32x2 FMA.
// ---------------------------------------------------------------------------
template <bool RELU_IN>
__global__ void __launch_bounds__(256)
proj_kernel(const float* __restrict__ hin,
            const float* __restrict__ W,     // [4,32,32]
            const float* __restrict__ Wl,    // [32,32]
            const float* __restrict__ bias,  // [32]
            float* __restrict__ hw,
            float* __restrict__ agg,
            int N)
{
    const int lane   = threadIdx.x & 31;
    const int warpId = (blockIdx.x * blockDim.x + threadIdx.x) >> 5;
    const int nWarps = (gridDim.x * blockDim.x) >> 5;

    // Weight columns for this lane, relations packed pairwise as f32x2.
    unsigned long long w01[32], w23[32];
    float w4[32];
#pragma unroll
    for (int k = 0; k < 32; k++) {
        float a = __ldg(W +           k * 32 + lane);   // W[0][k][lane]
        float b = __ldg(W + 1024 +    k * 32 + lane);   // W[1][k][lane]
        float c = __ldg(W + 2048 +    k * 32 + lane);   // W[2][k][lane]
        float d = __ldg(W + 3072 +    k * 32 + lane);   // W[3][k][lane]
        PACK2(w01[k], a, b);
        PACK2(w23[k], c, d);
        w4[k] = __ldg(Wl + k * 32 + lane);
    }
    const float bi = __ldg(bias + lane);

    for (int n = warpId; n < N; n += nWarps) {
        float xv = hin[(size_t)n * DD + lane];
        if (RELU_IN) xv = fmaxf(xv, 0.0f);

        unsigned long long a01a = 0ull, a01b = 0ull, a23a = 0ull, a23b = 0ull;
        float a4a = 0.0f, a4b = 0.0f;

#pragma unroll
        for (int k = 0; k < 32; k += 2) {
            float b0 = __shfl_sync(0xffffffffu, xv, k);
            float b1 = __shfl_sync(0xffffffffu, xv, k + 1);
            unsigned long long bb0, bb1;
            PACK2(bb0, b0, b0);
            PACK2(bb1, b1, b1);
            FMA2(a01a, bb0, w01[k],     a01a);
            FMA2(a23a, bb0, w23[k],     a23a);
            a4a = fmaf(b0, w4[k], a4a);
            FMA2(a01b, bb1, w01[k + 1], a01b);
            FMA2(a23b, bb1, w23[k + 1], a23b);
            a4b = fmaf(b1, w4[k + 1], a4b);
        }

        unsigned long long s01, s23;
        ADD2(s01, a01a, a01b);
        ADD2(s23, a23a, a23b);
        float r0, r1, r2, r3;
        UNPACK2(r0, r1, s01);
        UNPACK2(r2, r3, s23);

        float* hwn = hw + (size_t)n * (RR * DD);
        hwn[      lane] = r0;
        hwn[ 32 + lane] = r1;
        hwn[ 64 + lane] = r2;
        hwn[ 96 + lane] = r3;
        agg[(size_t)n * DD + lane] = a4a + a4b + bi;
    }
}

// ---------------------------------------------------------------------------
// edge kernel: agg[dst][:] += hw[src][etype][:]
// 8 lanes per edge, 128-bit vector reductions (target mostly L2-resident).
// ---------------------------------------------------------------------------
__global__ void edge_kernel(const float* __restrict__ hw,
                            const int* __restrict__ src,
                            const int* __restrict__ dst,
                            const int* __restrict__ et,
                            float* __restrict__ agg,
                            int E)
{
    int t = blockIdx.x * blockDim.x + threadIdx.x;
    int e = t >> 3;
    if (e >= E) return;
    int q = t & 7;

    int s = __ldg(src + e);
    int d = __ldg(dst + e);
    int r = __ldg(et + e);

    float4 v = __ldg(reinterpret_cast<const float4*>(hw) + ((size_t)s * RR + r) * 8 + q);
    float* p = agg + (size_t)d * DD + q * 4;
    asm volatile("red.global.add.v4.f32 [%0], {%1, %2, %3, %4};"
                 :: "l"(p), "f"(v.x), "f"(v.y), "f"(v.z), "f"(v.w)
                 : "memory");
}

// ---------------------------------------------------------------------------
// mean kernel: out[m][o] = mean_{a<32} relu(agg[(m*32+a)][o])
// ---------------------------------------------------------------------------
__global__ void mean_kernel(const float* __restrict__ agg,
                            float* __restrict__ out,
                            int M)
{
    int lane = threadIdx.x & 31;
    int m = (blockIdx.x * blockDim.x + threadIdx.x) >> 5;
    if (m >= M) return;
    float s = 0.0f;
#pragma unroll
    for (int a = 0; a < 32; a++)
        s += fmaxf(agg[((size_t)m * 32 + a) * DD + lane], 0.0f);
    out[(size_t)m * DD + lane] = s * (1.0f / 32.0f);
}

// ---------------------------------------------------------------------------
extern "C" void kernel_launch(void* const* d_in, const int* in_sizes, int n_in,
                              void* d_out, int out_size)
{
    const float* x    = (const float*)d_in[0];
    const float* W    = (const float*)d_in[1];
    const float* Wl   = (const float*)d_in[2];
    const float* bias = (const float*)d_in[3];
    const int*   src  = (const int*)d_in[4];
    const int*   dst  = (const int*)d_in[5];
    const int*   et   = (const int*)d_in[6];
    float* out = (float*)d_out;

    const int N = in_sizes[0] / DD;
    const int E = in_sizes[4];
    const int M = out_size / DD;

    void *hwP = nullptr, *aP = nullptr, *bP = nullptr;
    cudaGetSymbolAddress(&hwP, g_hw);
    cudaGetSymbolAddress(&aP, g_aggA);
    cudaGetSymbolAddress(&bP, g_aggB);
    float* hw   = (float*)hwP;
    float* aggA = (float*)aP;
    float* aggB = (float*)bP;

    const int edgeBlocks = (E * 8 + 255) / 256;
    const int projBlocks = 4096;
    const int meanBlocks = (M * 32 + 255) / 256;

    // ---- Layer 1 ----
    proj_kernel<false><<<projBlocks, 256>>>(x, W, Wl, bias, hw, aggA, N);
    edge_kernel<<<edgeBlocks, 256>>>(hw, src, dst, et, aggA, E);

    // ---- Layer 2 (relu fused into proj load) ----
    proj_kernel<true><<<projBlocks, 256>>>(aggA, W, Wl, bias, hw, aggB, N);
    edge_kernel<<<edgeBlocks, 256>>>(hw, src, dst, et, aggB, E);

    // ---- Per-molecule mean (relu fused) ----
    mean_kernel<<<meanBlocks, 256>>>(aggB, out, M);
}

// round 3
// speedup vs baseline: 1.9775x; 1.3805x over previous
#include <cuda_runtime.h>
#include <cuda_fp16.h>
#include <cstdint>

#define NMAX 1048576
#define EMAX 4194304
#define DD   32
#define RR   4

// Scratch (__device__ globals; no allocation allowed in kernel_launch)
__device__ __half g_hw[(size_t)NMAX * RR * DD];  // 256 MB: fp16 per-node per-relation projections
__device__ float  g_aggA[(size_t)NMAX * DD];     // 128 MB
__device__ float  g_aggB[(size_t)NMAX * DD];     // 128 MB

// ---- f32x2 packed helpers ---------------------------------------------------
#define FMA2(d, a, b, c) asm("fma.rn.f32x2 %0, %1, %2, %3;" : "=l"(d) : "l"(a), "l"(b), "l"(c))
#define ADD2(d, a, b)    asm("add.rn.f32x2 %0, %1, %2;"     : "=l"(d) : "l"(a), "l"(b))
#define PACK2(d, lo, hi) asm("mov.b64 %0, {%1, %2};"        : "=l"(d) : "f"(lo), "f"(hi))
#define UNPACK2(lo, hi, s) asm("mov.b64 {%0, %1}, %2;"      : "=f"(lo), "=f"(hi) : "l"(s))

// ---------------------------------------------------------------------------
// proj kernel: warp per 2 nodes (ILP), lane = output column o.
//   hw[n][r][o] = sum_k h[n][k] * W[r][k][o]   (fp16 store)
//   agg[n][o]   = sum_k h[n][k] * Wl[k][o] + bias[o]
// ---------------------------------------------------------------------------
#define PROJ_STEP(bq0, bq1, A01a, A23a, A4a, A01b, A23b, A4b, kk)                 \
    {                                                                             \
        unsigned long long bb0, bb1;                                             \
        PACK2(bb0, bq0, bq0);                                                     \
        PACK2(bb1, bq1, bq1);                                                     \
        FMA2(A01a, bb0, w01[kk],     A01a);                                       \
        FMA2(A23a, bb0, w23[kk],     A23a);                                       \
        A4a = fmaf(bq0, w4[kk], A4a);                                             \
        FMA2(A01b, bb1, w01[kk + 1], A01b);                                       \
        FMA2(A23b, bb1, w23[kk + 1], A23b);                                       \
        A4b = fmaf(bq1, w4[kk + 1], A4b);                                         \
    }

template <bool RELU_IN>
__global__ void __launch_bounds__(256, 1)
proj_kernel(const float* __restrict__ hin,
            const float* __restrict__ W,     // [4,32,32]
            const float* __restrict__ Wl,    // [32,32]
            const float* __restrict__ bias,  // [32]
            __half* __restrict__ hw,
            float* __restrict__ agg,
            int N)
{
    const int lane   = threadIdx.x & 31;
    const int warpId = (blockIdx.x * blockDim.x + threadIdx.x) >> 5;
    const int nWarps = (gridDim.x * blockDim.x) >> 5;
    const int P = N >> 1;   // node pairs

    unsigned long long w01[32], w23[32];
    float w4[32];
#pragma unroll
    for (int k = 0; k < 32; k++) {
        float a = __ldg(W +        k * 32 + lane);
        float b = __ldg(W + 1024 + k * 32 + lane);
        float c = __ldg(W + 2048 + k * 32 + lane);
        float d = __ldg(W + 3072 + k * 32 + lane);
        PACK2(w01[k], a, b);
        PACK2(w23[k], c, d);
        w4[k] = __ldg(Wl + k * 32 + lane);
    }
    const float bi = __ldg(bias + lane);

    for (int p = warpId; p < P; p += nWarps) {
        const int n0 = 2 * p, n1 = 2 * p + 1;
        float x0 = hin[(size_t)n0 * DD + lane];
        float x1 = hin[(size_t)n1 * DD + lane];
        if (RELU_IN) { x0 = fmaxf(x0, 0.0f); x1 = fmaxf(x1, 0.0f); }

        unsigned long long p01a = 0, p01b = 0, p23a = 0, p23b = 0;
        unsigned long long q01a = 0, q01b = 0, q23a = 0, q23b = 0;
        float p4a = 0.f, p4b = 0.f, q4a = 0.f, q4b = 0.f;

#pragma unroll
        for (int k = 0; k < 32; k += 2) {
            float b00 = __shfl_sync(0xffffffffu, x0, k);
            float b01 = __shfl_sync(0xffffffffu, x0, k + 1);
            float b10 = __shfl_sync(0xffffffffu, x1, k);
            float b11 = __shfl_sync(0xffffffffu, x1, k + 1);
            PROJ_STEP(b00, b01, p01a, p23a, p4a, p01b, p23b, p4b, k)
            PROJ_STEP(b10, b11, q01a, q23a, q4a, q01b, q23b, q4b, k)
        }

        unsigned long long s01, s23, t01, t23;
        ADD2(s01, p01a, p01b);  ADD2(s23, p23a, p23b);
        ADD2(t01, q01a, q01b);  ADD2(t23, q23a, q23b);
        float r0, r1, r2, r3, u0, u1, u2, u3;
        UNPACK2(r0, r1, s01);   UNPACK2(r2, r3, s23);
        UNPACK2(u0, u1, t01);   UNPACK2(u2, u3, t23);

        __half* h0 = hw + (size_t)n0 * (RR * DD);
        __half* h1 = hw + (size_t)n1 * (RR * DD);
        h0[      lane] = __float2half_rn(r0);
        h0[ 32 + lane] = __float2half_rn(r1);
        h0[ 64 + lane] = __float2half_rn(r2);
        h0[ 96 + lane] = __float2half_rn(r3);
        h1[      lane] = __float2half_rn(u0);
        h1[ 32 + lane] = __float2half_rn(u1);
        h1[ 64 + lane] = __float2half_rn(u2);
        h1[ 96 + lane] = __float2half_rn(u3);
        agg[(size_t)n0 * DD + lane] = p4a + p4b + bi;
        agg[(size_t)n1 * DD + lane] = q4a + q4b + bi;
    }
}

// ---------------------------------------------------------------------------
// edge kernel: agg[dst][:] += (float)hw[src][etype][:]
// 8 lanes per edge: lane q loads 4 halves (8B), REDs 16B of f32.
// ---------------------------------------------------------------------------
__global__ void edge_kernel(const __half* __restrict__ hw,
                            const int* __restrict__ src,
                            const int* __restrict__ dst,
                            const int* __restrict__ et,
                            float* __restrict__ agg,
                            int E)
{
    int t = blockIdx.x * blockDim.x + threadIdx.x;
    int e = t >> 3;
    if (e >= E) return;
    int q = t & 7;

    int s = __ldg(src + e);
    int d = __ldg(dst + e);
    int r = __ldg(et + e);

    const __half2* row = reinterpret_cast<const __half2*>(
        hw + ((size_t)s * RR + r) * DD);
    __half2 h01 = __ldg(row + q * 2);
    __half2 h23 = __ldg(row + q * 2 + 1);
    float2 f01 = __half22float2(h01);
    float2 f23 = __half22float2(h23);

    float* pdst = agg + (size_t)d * DD + q * 4;
    asm volatile("red.global.add.v4.f32 [%0], {%1, %2, %3, %4};"
                 :: "l"(pdst), "f"(f01.x), "f"(f01.y), "f"(f23.x), "f"(f23.y)
                 : "memory");
}

// ---------------------------------------------------------------------------
// mean kernel: out[m][o] = mean_a relu(agg[m*32+a][o])
// ---------------------------------------------------------------------------
__global__ void mean_kernel(const float* __restrict__ agg,
                            float* __restrict__ out,
                            int M)
{
    int lane = threadIdx.x & 31;
    int m = (blockIdx.x * blockDim.x + threadIdx.x) >> 5;
    if (m >= M) return;
    float s = 0.0f;
#pragma unroll
    for (int a = 0; a < 32; a++)
        s += fmaxf(agg[((size_t)m * 32 + a) * DD + lane], 0.0f);
    out[(size_t)m * DD + lane] = s * (1.0f / 32.0f);
}

// ---------------------------------------------------------------------------
extern "C" void kernel_launch(void* const* d_in, const int* in_sizes, int n_in,
                              void* d_out, int out_size)
{
    const float* x    = (const float*)d_in[0];
    const float* W    = (const float*)d_in[1];
    const float* Wl   = (const float*)d_in[2];
    const float* bias = (const float*)d_in[3];
    const int*   src  = (const int*)d_in[4];
    const int*   dst  = (const int*)d_in[5];
    const int*   et   = (const int*)d_in[6];
    float* out = (float*)d_out;

    const int N = in_sizes[0] / DD;
    const int E = in_sizes[4];
    const int M = out_size / DD;

    void *hwP = nullptr, *aP = nullptr, *bP = nullptr;
    cudaGetSymbolAddress(&hwP, g_hw);
    cudaGetSymbolAddress(&aP, g_aggA);
    cudaGetSymbolAddress(&bP, g_aggB);
    __half* hw  = (__half*)hwP;
    float* aggA = (float*)aP;
    float* aggB = (float*)bP;

    const int edgeBlocks = (E * 8 + 255) / 256;
    const int projBlocks = 4096;
    const int meanBlocks = (M * 32 + 255) / 256;

    // ---- Layer 1 ----
    proj_kernel<false><<<projBlocks, 256>>>(x, W, Wl, bias, hw, aggA, N);
    edge_kernel<<<edgeBlocks, 256>>>(hw, src, dst, et, aggA, E);

    // ---- Layer 2 (relu fused into proj load) ----
    proj_kernel<true><<<projBlocks, 256>>>(aggA, W, Wl, bias, hw, aggB, N);
    edge_kernel<<<edgeBlocks, 256>>>(hw, src, dst, et, aggB, E);

    // ---- Per-molecule mean (relu fused) ----
    mean_kernel<<<meanBlocks, 256>>>(aggB, out, M);
}

// round 4
// speedup vs baseline: 3.2433x; 1.6401x over previous
#include <cuda_runtime.h>
#include <cuda_fp16.h>
#include <cstdint>

#define NMAX 1048576
#define EMAX 4194304
#define DD   32
#define RR   4

// Scratch (__device__ globals; no allocation allowed in kernel_launch)
__device__ __half g_hw[(size_t)NMAX * RR * DD];  // 256 MB fp16 messages hw[n][r][o]
__device__ float  g_aggA[(size_t)NMAX * DD];     // 128 MB
__device__ float  g_aggB[(size_t)NMAX * DD];     // 128 MB

// ---------------------------------------------------------------------------
__device__ __forceinline__ unsigned pack_h2(float a, float b) {
    __half2 h = __floats2half2_rn(a, b);
    return *reinterpret_cast<unsigned*>(&h);
}

__device__ __forceinline__ void mma16816(float c[4], const unsigned a[4], const unsigned b[2]) {
    asm volatile("mma.sync.aligned.m16n8k16.row.col.f32.f16.f16.f32 "
                 "{%0,%1,%2,%3}, {%4,%5,%6,%7}, {%8,%9}, {%0,%1,%2,%3};"
                 : "+f"(c[0]), "+f"(c[1]), "+f"(c[2]), "+f"(c[3])
                 : "r"(a[0]), "r"(a[1]), "r"(a[2]), "r"(a[3]),
                   "r"(b[0]), "r"(b[1]));
}

// Wcat[k][c]: c<128 -> W[c>>5][k][c&31], c>=128 -> Wl[k][c-128]
__device__ __forceinline__ float wcat(const float* __restrict__ W,
                                      const float* __restrict__ Wl,
                                      int k, int c) {
    return (c < 128) ? __ldg(W + (c >> 5) * 1024 + k * 32 + (c & 31))
                     : __ldg(Wl + k * 32 + (c - 128));
}

// ---------------------------------------------------------------------------
// proj via tensor cores: per 16-node tile,
//   hw[n][c]  (c<128, fp16)  = h[n] @ Wcat[:,c]
//   agg[n][o] (f32)          = h[n] @ Wl[:,o] + bias[o]
// Warp computes [16 x 160] with 40 HMMA m16n8k16 (B frags held in registers).
// ---------------------------------------------------------------------------
template <bool RELU_IN>
__global__ void __launch_bounds__(256)
proj_mma(const float* __restrict__ hin,
         const float* __restrict__ W,     // [4,32,32]
         const float* __restrict__ Wl,    // [32,32]
         const float* __restrict__ bias,  // [32]
         __half* __restrict__ hw,
         float* __restrict__ agg,
         int nTiles)
{
    const int lane   = threadIdx.x & 31;
    const int warpId = (blockIdx.x * blockDim.x + threadIdx.x) >> 5;
    const int nWarps = (gridDim.x * blockDim.x) >> 5;

    const int kq = 2 * (lane & 3);   // k / output-col phase within octet
    const int nq = lane >> 2;        // row within tile / col group element

    // B fragments: 20 n-groups x 2 k-steps x 2 regs
    unsigned bf[20][2][2];
#pragma unroll
    for (int g = 0; g < 20; g++) {
#pragma unroll
        for (int s = 0; s < 2; s++) {
            const int c  = 8 * g + nq;
            const int k0 = 16 * s + kq;
            bf[g][s][0] = pack_h2(wcat(W, Wl, k0,     c), wcat(W, Wl, k0 + 1, c));
            bf[g][s][1] = pack_h2(wcat(W, Wl, k0 + 8, c), wcat(W, Wl, k0 + 9, c));
        }
    }

    float2 bvec[4];
#pragma unroll
    for (int gg = 0; gg < 4; gg++) {
        const int o = 8 * gg + kq;
        bvec[gg] = make_float2(__ldg(bias + o), __ldg(bias + o + 1));
    }

    for (int t = warpId; t < nTiles; t += nWarps) {
        const int m0 = t * 16;
        const float* r0 = hin + (size_t)(m0 + nq) * DD + kq;
        const float* r1 = r0 + 8 * DD;

        float2 x0a = *(const float2*)(r0);
        float2 x0b = *(const float2*)(r0 + 8);
        float2 x0c = *(const float2*)(r0 + 16);
        float2 x0d = *(const float2*)(r0 + 24);
        float2 x1a = *(const float2*)(r1);
        float2 x1b = *(const float2*)(r1 + 8);
        float2 x1c = *(const float2*)(r1 + 16);
        float2 x1d = *(const float2*)(r1 + 24);

        if (RELU_IN) {
            x0a.x = fmaxf(x0a.x, 0.f); x0a.y = fmaxf(x0a.y, 0.f);
            x0b.x = fmaxf(x0b.x, 0.f); x0b.y = fmaxf(x0b.y, 0.f);
            x0c.x = fmaxf(x0c.x, 0.f); x0c.y = fmaxf(x0c.y, 0.f);
            x0d.x = fmaxf(x0d.x, 0.f); x0d.y = fmaxf(x0d.y, 0.f);
            x1a.x = fmaxf(x1a.x, 0.f); x1a.y = fmaxf(x1a.y, 0.f);
            x1b.x = fmaxf(x1b.x, 0.f); x1b.y = fmaxf(x1b.y, 0.f);
            x1c.x = fmaxf(x1c.x, 0.f); x1c.y = fmaxf(x1c.y, 0.f);
            x1d.x = fmaxf(x1d.x, 0.f); x1d.y = fmaxf(x1d.y, 0.f);
        }

        // A fragments (row-major m16k16): R0={row nq,k}, R1={row nq+8,k},
        // R2={row nq,k+8}, R3={row nq+8,k+8}
        unsigned A0[4] = { pack_h2(x0a.x, x0a.y), pack_h2(x1a.x, x1a.y),
                           pack_h2(x0b.x, x0b.y), pack_h2(x1b.x, x1b.y) };
        unsigned A1[4] = { pack_h2(x0c.x, x0c.y), pack_h2(x1c.x, x1c.y),
                           pack_h2(x0d.x, x0d.y), pack_h2(x1d.x, x1d.y) };

        float acc[20][4];
#pragma unroll
        for (int g = 0; g < 20; g++) {
            acc[g][0] = 0.f; acc[g][1] = 0.f; acc[g][2] = 0.f; acc[g][3] = 0.f;
        }
#pragma unroll
        for (int g = 0; g < 20; g++) {
            mma16816(acc[g], A0, bf[g][0]);
            mma16816(acc[g], A1, bf[g][1]);
        }

        // Messages: groups 0..15 -> hw fp16
        __half* hw0 = hw + (size_t)(m0 + nq) * 128 + kq;
        __half* hw1 = hw + (size_t)(m0 + nq + 8) * 128 + kq;
#pragma unroll
        for (int g = 0; g < 16; g++) {
            *reinterpret_cast<__half2*>(hw0 + 8 * g) = __floats2half2_rn(acc[g][0], acc[g][1]);
            *reinterpret_cast<__half2*>(hw1 + 8 * g) = __floats2half2_rn(acc[g][2], acc[g][3]);
        }
        // Self-loop + bias: groups 16..19 -> agg f32
        float* ag0 = agg + (size_t)(m0 + nq) * DD + kq;
        float* ag1 = agg + (size_t)(m0 + nq + 8) * DD + kq;
#pragma unroll
        for (int gg = 0; gg < 4; gg++) {
            const int g = 16 + gg;
            *reinterpret_cast<float2*>(ag0 + 8 * gg) =
                make_float2(acc[g][0] + bvec[gg].x, acc[g][1] + bvec[gg].y);
            *reinterpret_cast<float2*>(ag1 + 8 * gg) =
                make_float2(acc[g][2] + bvec[gg].x, acc[g][3] + bvec[gg].y);
        }
    }
}

// ---------------------------------------------------------------------------
// edge kernel: agg[dst][:] += (float)hw[src][etype][:]
// ---------------------------------------------------------------------------
__global__ void edge_kernel(const __half* __restrict__ hw,
                            const int* __restrict__ src,
                            const int* __restrict__ dst,
                            const int* __restrict__ et,
                            float* __restrict__ agg,
                            int E)
{
    int t = blockIdx.x * blockDim.x + threadIdx.x;
    int e = t >> 3;
    if (e >= E) return;
    int q = t & 7;

    int s = __ldg(src + e);
    int d = __ldg(dst + e);
    int r = __ldg(et + e);

    const __half2* row = reinterpret_cast<const __half2*>(hw + ((size_t)s * RR + r) * DD);
    float2 f01 = __half22float2(__ldg(row + q * 2));
    float2 f23 = __half22float2(__ldg(row + q * 2 + 1));

    float* pdst = agg + (size_t)d * DD + q * 4;
    asm volatile("red.global.add.v4.f32 [%0], {%1, %2, %3, %4};"
                 :: "l"(pdst), "f"(f01.x), "f"(f01.y), "f"(f23.x), "f"(f23.y)
                 : "memory");
}

// ---------------------------------------------------------------------------
__global__ void mean_kernel(const float* __restrict__ agg,
                            float* __restrict__ out,
                            int M)
{
    int lane = threadIdx.x & 31;
    int m = (blockIdx.x * blockDim.x + threadIdx.x) >> 5;
    if (m >= M) return;
    float s = 0.0f;
#pragma unroll
    for (int a = 0; a < 32; a++)
        s += fmaxf(agg[((size_t)m * 32 + a) * DD + lane], 0.0f);
    out[(size_t)m * DD + lane] = s * (1.0f / 32.0f);
}

// ---------------------------------------------------------------------------
extern "C" void kernel_launch(void* const* d_in, const int* in_sizes, int n_in,
                              void* d_out, int out_size)
{
    const float* x    = (const float*)d_in[0];
    const float* W    = (const float*)d_in[1];
    const float* Wl   = (const float*)d_in[2];
    const float* bias = (const float*)d_in[3];
    const int*   src  = (const int*)d_in[4];
    const int*   dst  = (const int*)d_in[5];
    const int*   et   = (const int*)d_in[6];
    float* out = (float*)d_out;

    const int N = in_sizes[0] / DD;
    const int E = in_sizes[4];
    const int M = out_size / DD;
    const int nTiles = N / 16;

    void *hwP = nullptr, *aP = nullptr, *bP = nullptr;
    cudaGetSymbolAddress(&hwP, g_hw);
    cudaGetSymbolAddress(&aP, g_aggA);
    cudaGetSymbolAddress(&bP, g_aggB);
    __half* hwp = (__half*)hwP;
    float* aggA = (float*)aP;
    float* aggB = (float*)bP;

    const int edgeBlocks = (E * 8 + 255) / 256;
    const int projBlocks = 1024;
    const int meanBlocks = (M * 32 + 255) / 256;

    // ---- Layer 1 ----
    proj_mma<false><<<projBlocks, 256>>>(x, W, Wl, bias, hwp, aggA, nTiles);
    edge_kernel<<<edgeBlocks, 256>>>(hwp, src, dst, et, aggA, E);

    // ---- Layer 2 (relu fused into proj A-load) ----
    proj_mma<true><<<projBlocks, 256>>>(aggA, W, Wl, bias, hwp, aggB, nTiles);
    edge_kernel<<<edgeBlocks, 256>>>(hwp, src, dst, et, aggB, E);

    // ---- Per-molecule mean (relu fused) ----
    mean_kernel<<<meanBlocks, 256>>>(aggB, out, M);
}